// round 16
// baseline (speedup 1.0000x reference)
#include <cuda_runtime.h>
#include <cuda_fp16.h>
#include <math.h>

#define N_NODES 260000
#define N_EDGES 8320000
#define N_GRAPHS 10000
#define GN 26

// ---- device-global scratch (zero-initialized at module load; kernels restore
// zeros / overwrite after consuming, so every graph replay re-enters a clean state) ----
__device__ uint4 g_xs[N_NODES];         // accum: [sum x f16 x4 | deg f16 | pad]
__device__ uint4 g_zh[N_NODES * 2];     // z in f16: 11 halves used, 32B stride
__device__ uint4 g_aggA[N_NODES];       // agg ch0-7 (seeded z_self + c1*b2), f16 accum
__device__ uint2 g_aggB[N_NODES];       // agg ch8-10 (seeded z_self + c1*b2), f16 accum

__device__ __forceinline__ void redh8(void* p, unsigned a, unsigned b, unsigned c, unsigned d) {
    asm volatile("red.global.add.noftz.v4.f16x2 [%0], {%1,%2,%3,%4};"
                 :: "l"(__cvta_generic_to_global(p)), "r"(a), "r"(b), "r"(c), "r"(d)
                 : "memory");
}
__device__ __forceinline__ void redh4(void* p, unsigned a, unsigned b) {
    asm volatile("red.global.add.noftz.v2.f16x2 [%0], {%1,%2};"
                 :: "l"(__cvta_generic_to_global(p)), "r"(a), "r"(b)
                 : "memory");
}
__device__ __forceinline__ unsigned packh2(float a, float b) {
    __half2 h = __floats2half2_rn(a, b);
    return *reinterpret_cast<unsigned*>(&h);
}
__device__ __forceinline__ float2 unpackh2(unsigned u) {
    __half2 h = *reinterpret_cast<__half2*>(&u);
    return __half22float2(h);
}
// two tanh per MUFU op
__device__ __forceinline__ float2 tanh2fast(float a, float b) {
    unsigned in = packh2(a, b), out;
    asm("tanh.approx.f16x2 %0, %1;" : "=r"(out) : "r"(in));
    return unpackh2(out);
}

// ---------------- K1: edge pass 1 — gather f32 x, pack, ONE red.v4.f16x2 ----------------
__global__ void edge1_kernel(const int* __restrict__ ei, const float4* __restrict__ x) {
    int e = blockIdx.x * blockDim.x + threadIdx.x;
    if (e >= N_EDGES) return;
    int r = __ldcs(&ei[e]);
    int c = __ldcs(&ei[N_EDGES + e]);
    float4 v = __ldg(&x[r]);
    // halves: [x0,x1, x2,x3, 1.0,0, 0,0] -> deg counts exactly in f16
    redh8(&g_xs[c], packh2(v.x, v.y), packh2(v.z, v.w), 0x00003C00u, 0u);
}

// ---------------- K2: node pass 1 — PDL: stage weights, then sync on edge1;
//                  consume+zero g_xs; h1=tanh; z=h1@W2^T; seed aggs ----------------
__global__ void node1_kernel(const float4* __restrict__ x,
                             const float* __restrict__ W1,
                             const float* __restrict__ b1,
                             const float* __restrict__ W2,
                             const float* __restrict__ b2) {
    __shared__ float sW1[26 * 4];
    __shared__ float sb1[26];
    __shared__ float sW2[11 * 26];
    __shared__ float sb2[11];
    int t = threadIdx.x;
    for (int i = t; i < 26 * 4; i += blockDim.x)  sW1[i] = W1[i];
    for (int i = t; i < 26; i += blockDim.x)      sb1[i] = b1[i];
    for (int i = t; i < 11 * 26; i += blockDim.x) sW2[i] = W2[i];
    if (t < 11) sb2[t] = b2[t];
    __syncthreads();

    int i = blockIdx.x * blockDim.x + t;
    float4 xi;
    if (i < N_NODES) xi = __ldg(&x[i]);       // input-only, safe pre-sync

#if __CUDA_ARCH__ >= 900
    cudaGridDependencySynchronize();          // wait for edge1's atomics
#endif
    if (i >= N_NODES) return;

    uint4 sv = g_xs[i];
    g_xs[i] = make_uint4(0u, 0u, 0u, 0u);     // restore zero state for next replay
    float2 s01 = unpackh2(sv.x), s23 = unpackh2(sv.y);
    float  deg = unpackh2(sv.z).x;
    float t0 = s01.x + xi.x, t1 = s01.y + xi.y;
    float t2 = s23.x + xi.z, t3 = s23.y + xi.w;
    float c1 = deg + 1.0f;

    float a[26];
#pragma unroll
    for (int j = 0; j < 26; j++) {
        a[j] = fmaf(sW1[j * 4 + 0], t0,
               fmaf(sW1[j * 4 + 1], t1,
               fmaf(sW1[j * 4 + 2], t2,
               fmaf(sW1[j * 4 + 3], t3, c1 * sb1[j]))));
    }
    float h[26];
#pragma unroll
    for (int j = 0; j < 26; j += 2) {
        float2 hp = tanh2fast(a[j], a[j + 1]);   // 1 MUFU per 2 channels
        h[j] = hp.x; h[j + 1] = hp.y;
    }

    float z[11];
#pragma unroll
    for (int k = 0; k < 11; k++) {
        float acc = 0.f;
#pragma unroll
        for (int j = 0; j < 26; j++) acc = fmaf(sW2[k * 26 + j], h[j], acc);
        z[k] = acc;
    }

    // pure z record for the edge-2 gather
    uint4 A;
    A.x = packh2(z[0], z[1]);  A.y = packh2(z[2], z[3]);
    A.z = packh2(z[4], z[5]);  A.w = packh2(z[6], z[7]);
    g_zh[i * 2]     = A;
    g_zh[i * 2 + 1] = make_uint4(packh2(z[8], z[9]), packh2(z[10], 0.f), 0u, 0u);

    // seed aggs with self-loop z + folded bias c1*b2 (f32, packed once)
    float u[11];
#pragma unroll
    for (int k = 0; k < 11; k++) u[k] = fmaf(c1, sb2[k], z[k]);
    g_aggA[i] = make_uint4(packh2(u[0], u[1]), packh2(u[2], u[3]),
                           packh2(u[4], u[5]), packh2(u[6], u[7]));
    g_aggB[i] = make_uint2(packh2(u[8], u[9]), packh2(u[10], 0.f));
}

// ---------------- K3: edge pass 2 — PDL: stream indices early, sync, gather + 2 REDs ----------------
__global__ void edge2_kernel(const int* __restrict__ ei) {
    int e = blockIdx.x * blockDim.x + threadIdx.x;
    int r = 0, c = 0;
    if (e < N_EDGES) {
        r = __ldcs(&ei[e]);                   // input-only: overlap with node1
        c = __ldcs(&ei[N_EDGES + e]);
    }
#if __CUDA_ARCH__ >= 900
    cudaGridDependencySynchronize();          // wait for node1's z/agg writes
#endif
    if (e >= N_EDGES) return;

    const uint4* zp = &g_zh[r * 2];
    uint4 A = __ldg(zp);                            // ch0..7
    uint2 B = __ldg((const uint2*)(zp + 1));        // ch8..10 + 0-pad, same 32B sector

    redh8(&g_aggA[c], A.x, A.y, A.z, A.w);
    redh4(&g_aggB[c], B.x, B.y);                    // pad lane += 0.0 (exact)
}

// ---------------- K4: warp-per-graph — PDL prologue; maxpool(pre-act), 4x tanh,
//                  26-sum, linear, softmax ----------------
__global__ void node2final_kernel(const float* __restrict__ Wl,
                                  const float* __restrict__ bl,
                                  float2* __restrict__ out) {
    __shared__ float sWl[8];
    __shared__ float sbl[2];
    int t = threadIdx.x;
    if (t < 8) sWl[t] = Wl[t];
    if (t < 2) sbl[t] = bl[t];
    __syncthreads();
#if __CUDA_ARCH__ >= 900
    cudaGridDependencySynchronize();          // wait for edge2's atomics
#endif

    int gw   = (blockIdx.x * blockDim.x + t) >> 5;
    int lane = t & 31;
    if (gw >= N_GRAPHS) return;

    float p0 = 0.f, p1 = 0.f, p2 = 0.f, p3 = 0.f;
    if (lane < GN) {
        int i = gw * GN + lane;
        uint4 A = __ldcs(&g_aggA[i]);         // read-once streaming
        uint2 B = __ldcs(&g_aggB[i]);
        float2 u01 = unpackh2(A.x), u23 = unpackh2(A.y);
        float2 u45 = unpackh2(A.z), u67 = unpackh2(A.w);
        float2 u89 = unpackh2(B.x), uA_ = unpackh2(B.y);

        // bias folded into accumulators by node1's seed.
        // tanh monotonic: maxpool pre-activations, then 4 tanh.
        // MaxPool1d(3, stride 3, left-pad 1)
        float m0 = fmaxf(u01.x, u01.y);
        float m1 = fmaxf(fmaxf(u23.x, u23.y), u45.x);
        float m2 = fmaxf(fmaxf(u45.y, u67.x), u67.y);
        float m3 = fmaxf(fmaxf(u89.x, u89.y), uA_.x);
        float2 q01 = tanh2fast(m0, m1);
        float2 q23 = tanh2fast(m2, m3);
        p0 = q01.x; p1 = q01.y; p2 = q23.x; p3 = q23.y;
    }

#pragma unroll
    for (int o = 16; o > 0; o >>= 1) {
        p0 += __shfl_xor_sync(0xFFFFFFFFu, p0, o);
        p1 += __shfl_xor_sync(0xFFFFFFFFu, p1, o);
        p2 += __shfl_xor_sync(0xFFFFFFFFu, p2, o);
        p3 += __shfl_xor_sync(0xFFFFFFFFu, p3, o);
    }

    if (lane == 0) {
        float o0 = fmaf(sWl[0], p0, fmaf(sWl[1], p1, fmaf(sWl[2], p2, fmaf(sWl[3], p3, sbl[0]))));
        float o1 = fmaf(sWl[4], p0, fmaf(sWl[5], p1, fmaf(sWl[6], p2, fmaf(sWl[7], p3, sbl[1]))));
        float m = fmaxf(o0, o1);
        float e0 = expf(o0 - m), e1 = expf(o1 - m);
        float inv = 1.0f / (e0 + e1);
        out[gw] = make_float2(e0 * inv, e1 * inv);
    }
}

// host-side PDL launcher (stream 0 == same stream <<<>>> uses; capturable)
static void launch_pdl(const void* fn, int grid, int block, void** args) {
    cudaLaunchConfig_t cfg = {};
    cfg.gridDim  = dim3((unsigned)grid, 1, 1);
    cfg.blockDim = dim3((unsigned)block, 1, 1);
    cfg.dynamicSmemBytes = 0;
    cfg.stream = 0;
    cudaLaunchAttribute attr[1];
    attr[0].id = cudaLaunchAttributeProgrammaticStreamSerialization;
    attr[0].val.programmaticStreamSerializationAllowed = 1;
    cfg.attrs = attr;
    cfg.numAttrs = 1;
    cudaLaunchKernelExC(&cfg, fn, args);
}

extern "C" void kernel_launch(void* const* d_in, const int* in_sizes, int n_in,
                              void* d_out, int out_size) {
    const float4* x  = (const float4*)d_in[0];   // [260000,4] f32
    const int*    ei = (const int*)d_in[1];      // [2, 8320000] i32
    const float*  W1 = (const float*)d_in[2];
    const float*  b1 = (const float*)d_in[3];
    const float*  W2 = (const float*)d_in[4];
    const float*  b2 = (const float*)d_in[5];
    const float*  Wl = (const float*)d_in[6];
    const float*  bl = (const float*)d_in[7];
    float2* out = (float2*)d_out;                // [10000,2]

    const int TE = 512;                          // edge kernels: deeper per-SM RED queue
    const int T  = 256;
    const int EB = (N_EDGES + TE - 1) / TE;
    const int NB = (N_NODES + T - 1) / T;
    const int GB = (N_GRAPHS * 32 + T - 1) / T;

    edge1_kernel<<<EB, TE>>>(ei, x);

    {   // node1: overlap weight staging + x loads with edge1 tail
        void* args[] = {(void*)&x, (void*)&W1, (void*)&b1, (void*)&W2, (void*)&b2};
        launch_pdl((const void*)node1_kernel, NB, T, args);
    }
    {   // edge2: overlap index streaming with node1
        void* args[] = {(void*)&ei};
        launch_pdl((const void*)edge2_kernel, EB, TE, args);
    }
    {   // node2final: overlap param staging with edge2 tail
        void* args[] = {(void*)&Wl, (void*)&bl, (void*)&out};
        launch_pdl((const void*)node2final_kernel, GB, T, args);
    }
}

// round 17
// speedup vs baseline: 1.0039x; 1.0039x over previous
#include <cuda_runtime.h>
#include <cuda_fp16.h>
#include <math.h>

#define N_NODES 260000
#define N_EDGES 8320000
#define N_GRAPHS 10000
#define GN 26

// ---- device-global scratch (zero-initialized at module load; kernels restore
// zeros / overwrite after consuming, so every graph replay re-enters a clean state) ----
__device__ uint4 g_xs[N_NODES];         // accum: [sum x f16 x4 | deg f16 | pad]
__device__ uint4 g_zh[N_NODES * 2];     // z in f16: 11 halves used, 32B stride
__device__ uint4 g_aggA[N_NODES];       // agg ch0-7 (seeded z_self + c1*b2), f16 accum
__device__ uint2 g_aggB[N_NODES];       // agg ch8-10 (seeded z_self + c1*b2), f16 accum

__device__ __forceinline__ void redh8(void* p, unsigned a, unsigned b, unsigned c, unsigned d) {
    asm volatile("red.global.add.noftz.v4.f16x2 [%0], {%1,%2,%3,%4};"
                 :: "l"(__cvta_generic_to_global(p)), "r"(a), "r"(b), "r"(c), "r"(d)
                 : "memory");
}
__device__ __forceinline__ void redh4(void* p, unsigned a, unsigned b) {
    asm volatile("red.global.add.noftz.v2.f16x2 [%0], {%1,%2};"
                 :: "l"(__cvta_generic_to_global(p)), "r"(a), "r"(b)
                 : "memory");
}
__device__ __forceinline__ unsigned packh2(float a, float b) {
    __half2 h = __floats2half2_rn(a, b);
    return *reinterpret_cast<unsigned*>(&h);
}
__device__ __forceinline__ float2 unpackh2(unsigned u) {
    __half2 h = *reinterpret_cast<__half2*>(&u);
    return __half22float2(h);
}
// two tanh per MUFU op
__device__ __forceinline__ float2 tanh2fast(float a, float b) {
    unsigned in = packh2(a, b), out;
    asm("tanh.approx.f16x2 %0, %1;" : "=r"(out) : "r"(in));
    return unpackh2(out);
}

// ---------------- K1: edge pass 1 — gather f32 x, pack, ONE red.v4.f16x2 ----------------
__global__ void edge1_kernel(const int* __restrict__ ei, const float4* __restrict__ x) {
    int e = blockIdx.x * blockDim.x + threadIdx.x;
    if (e >= N_EDGES) return;
    int r = __ldcs(&ei[e]);
    int c = __ldcs(&ei[N_EDGES + e]);
    float4 v = __ldg(&x[r]);
    // halves: [x0,x1, x2,x3, 1.0,0, 0,0] -> deg counts exactly in f16
    redh8(&g_xs[c], packh2(v.x, v.y), packh2(v.z, v.w), 0x00003C00u, 0u);
}

// ---------------- K2: node pass 1 — PDL: stage weights, then sync on edge1;
//                  consume+zero g_xs; h1=tanh; z=h1@W2^T; seed aggs ----------------
__global__ void node1_kernel(const float4* __restrict__ x,
                             const float* __restrict__ W1,
                             const float* __restrict__ b1,
                             const float* __restrict__ W2,
                             const float* __restrict__ b2) {
    __shared__ float sW1[26 * 4];
    __shared__ float sb1[26];
    __shared__ float sW2[11 * 26];
    __shared__ float sb2[11];
    int t = threadIdx.x;
    for (int i = t; i < 26 * 4; i += blockDim.x)  sW1[i] = W1[i];
    for (int i = t; i < 26; i += blockDim.x)      sb1[i] = b1[i];
    for (int i = t; i < 11 * 26; i += blockDim.x) sW2[i] = W2[i];
    if (t < 11) sb2[t] = b2[t];
    __syncthreads();

    int i = blockIdx.x * blockDim.x + t;
    float4 xi;
    if (i < N_NODES) xi = __ldg(&x[i]);       // input-only, safe pre-sync

#if __CUDA_ARCH__ >= 900
    cudaGridDependencySynchronize();          // wait for edge1's atomics
#endif
    if (i >= N_NODES) return;

    uint4 sv = g_xs[i];
    g_xs[i] = make_uint4(0u, 0u, 0u, 0u);     // restore zero state for next replay
    float2 s01 = unpackh2(sv.x), s23 = unpackh2(sv.y);
    float  deg = unpackh2(sv.z).x;
    float t0 = s01.x + xi.x, t1 = s01.y + xi.y;
    float t2 = s23.x + xi.z, t3 = s23.y + xi.w;
    float c1 = deg + 1.0f;

    float a[26];
#pragma unroll
    for (int j = 0; j < 26; j++) {
        a[j] = fmaf(sW1[j * 4 + 0], t0,
               fmaf(sW1[j * 4 + 1], t1,
               fmaf(sW1[j * 4 + 2], t2,
               fmaf(sW1[j * 4 + 3], t3, c1 * sb1[j]))));
    }
    float h[26];
#pragma unroll
    for (int j = 0; j < 26; j += 2) {
        float2 hp = tanh2fast(a[j], a[j + 1]);   // 1 MUFU per 2 channels
        h[j] = hp.x; h[j + 1] = hp.y;
    }

    float z[11];
#pragma unroll
    for (int k = 0; k < 11; k++) {
        float acc = 0.f;
#pragma unroll
        for (int j = 0; j < 26; j++) acc = fmaf(sW2[k * 26 + j], h[j], acc);
        z[k] = acc;
    }

    // pure z record for the edge-2 gather
    uint4 A;
    A.x = packh2(z[0], z[1]);  A.y = packh2(z[2], z[3]);
    A.z = packh2(z[4], z[5]);  A.w = packh2(z[6], z[7]);
    g_zh[i * 2]     = A;
    g_zh[i * 2 + 1] = make_uint4(packh2(z[8], z[9]), packh2(z[10], 0.f), 0u, 0u);

    // seed aggs with self-loop z + folded bias c1*b2 (f32, packed once)
    float u[11];
#pragma unroll
    for (int k = 0; k < 11; k++) u[k] = fmaf(c1, sb2[k], z[k]);
    g_aggA[i] = make_uint4(packh2(u[0], u[1]), packh2(u[2], u[3]),
                           packh2(u[4], u[5]), packh2(u[6], u[7]));
    g_aggB[i] = make_uint2(packh2(u[8], u[9]), packh2(u[10], 0.f));
}

// ---------------- K3: edge pass 2 — PDL: stream indices early, sync, gather + 2 REDs ----------------
__global__ void edge2_kernel(const int* __restrict__ ei) {
    int e = blockIdx.x * blockDim.x + threadIdx.x;
    int r = 0, c = 0;
    if (e < N_EDGES) {
        r = __ldcs(&ei[e]);                   // input-only: overlap with node1
        c = __ldcs(&ei[N_EDGES + e]);
    }
#if __CUDA_ARCH__ >= 900
    cudaGridDependencySynchronize();          // wait for node1's z/agg writes
#endif
    if (e >= N_EDGES) return;

    const uint4* zp = &g_zh[r * 2];
    uint4 A = __ldg(zp);                            // ch0..7
    uint2 B = __ldg((const uint2*)(zp + 1));        // ch8..10 + 0-pad, same 32B sector

    redh8(&g_aggA[c], A.x, A.y, A.z, A.w);
    redh4(&g_aggB[c], B.x, B.y);                    // pad lane += 0.0 (exact)
}

// ---------------- K4: warp-per-graph — PDL prologue; maxpool(pre-act), 4x tanh,
//                  26-sum, linear, softmax ----------------
__global__ void node2final_kernel(const float* __restrict__ Wl,
                                  const float* __restrict__ bl,
                                  float2* __restrict__ out) {
    __shared__ float sWl[8];
    __shared__ float sbl[2];
    int t = threadIdx.x;
    if (t < 8) sWl[t] = Wl[t];
    if (t < 2) sbl[t] = bl[t];
    __syncthreads();
#if __CUDA_ARCH__ >= 900
    cudaGridDependencySynchronize();          // wait for edge2's atomics
#endif

    int gw   = (blockIdx.x * blockDim.x + t) >> 5;
    int lane = t & 31;
    if (gw >= N_GRAPHS) return;

    float p0 = 0.f, p1 = 0.f, p2 = 0.f, p3 = 0.f;
    if (lane < GN) {
        int i = gw * GN + lane;
        uint4 A = __ldcs(&g_aggA[i]);         // read-once streaming
        uint2 B = __ldcs(&g_aggB[i]);
        float2 u01 = unpackh2(A.x), u23 = unpackh2(A.y);
        float2 u45 = unpackh2(A.z), u67 = unpackh2(A.w);
        float2 u89 = unpackh2(B.x), uA_ = unpackh2(B.y);

        // bias folded into accumulators by node1's seed.
        // tanh monotonic: maxpool pre-activations, then 4 tanh.
        // MaxPool1d(3, stride 3, left-pad 1)
        float m0 = fmaxf(u01.x, u01.y);
        float m1 = fmaxf(fmaxf(u23.x, u23.y), u45.x);
        float m2 = fmaxf(fmaxf(u45.y, u67.x), u67.y);
        float m3 = fmaxf(fmaxf(u89.x, u89.y), uA_.x);
        float2 q01 = tanh2fast(m0, m1);
        float2 q23 = tanh2fast(m2, m3);
        p0 = q01.x; p1 = q01.y; p2 = q23.x; p3 = q23.y;
    }

#pragma unroll
    for (int o = 16; o > 0; o >>= 1) {
        p0 += __shfl_xor_sync(0xFFFFFFFFu, p0, o);
        p1 += __shfl_xor_sync(0xFFFFFFFFu, p1, o);
        p2 += __shfl_xor_sync(0xFFFFFFFFu, p2, o);
        p3 += __shfl_xor_sync(0xFFFFFFFFu, p3, o);
    }

    if (lane == 0) {
        float o0 = fmaf(sWl[0], p0, fmaf(sWl[1], p1, fmaf(sWl[2], p2, fmaf(sWl[3], p3, sbl[0]))));
        float o1 = fmaf(sWl[4], p0, fmaf(sWl[5], p1, fmaf(sWl[6], p2, fmaf(sWl[7], p3, sbl[1]))));
        float m = fmaxf(o0, o1);
        float e0 = expf(o0 - m), e1 = expf(o1 - m);
        float inv = 1.0f / (e0 + e1);
        out[gw] = make_float2(e0 * inv, e1 * inv);
    }
}

// host-side PDL launcher (stream 0 == same stream <<<>>> uses; capturable)
static void launch_pdl(const void* fn, int grid, int block, void** args) {
    cudaLaunchConfig_t cfg = {};
    cfg.gridDim  = dim3((unsigned)grid, 1, 1);
    cfg.blockDim = dim3((unsigned)block, 1, 1);
    cfg.dynamicSmemBytes = 0;
    cfg.stream = 0;
    cudaLaunchAttribute attr[1];
    attr[0].id = cudaLaunchAttributeProgrammaticStreamSerialization;
    attr[0].val.programmaticStreamSerializationAllowed = 1;
    cfg.attrs = attr;
    cfg.numAttrs = 1;
    cudaLaunchKernelExC(&cfg, fn, args);
}

extern "C" void kernel_launch(void* const* d_in, const int* in_sizes, int n_in,
                              void* d_out, int out_size) {
    const float4* x  = (const float4*)d_in[0];   // [260000,4] f32
    const int*    ei = (const int*)d_in[1];      // [2, 8320000] i32
    const float*  W1 = (const float*)d_in[2];
    const float*  b1 = (const float*)d_in[3];
    const float*  W2 = (const float*)d_in[4];
    const float*  b2 = (const float*)d_in[5];
    const float*  Wl = (const float*)d_in[6];
    const float*  bl = (const float*)d_in[7];
    float2* out = (float2*)d_out;                // [10000,2]

    const int T  = 256;
    const int EB = (N_EDGES + T - 1) / T;
    const int NB = (N_NODES + T - 1) / T;
    const int GB = (N_GRAPHS * 32 + T - 1) / T;

    edge1_kernel<<<EB, T>>>(ei, x);

    {   // node1: overlap weight staging + x loads with edge1 tail
        void* args[] = {(void*)&x, (void*)&W1, (void*)&b1, (void*)&W2, (void*)&b2};
        launch_pdl((const void*)node1_kernel, NB, T, args);
    }
    {   // edge2: overlap index streaming with node1
        void* args[] = {(void*)&ei};
        launch_pdl((const void*)edge2_kernel, EB, T, args);
    }
    {   // node2final: overlap param staging with edge2 tail
        void* args[] = {(void*)&Wl, (void*)&bl, (void*)&out};
        launch_pdl((const void*)node2final_kernel, GB, T, args);
    }
}